// round 1
// baseline (speedup 1.0000x reference)
#include <cuda_runtime.h>
#include <cstdint>
#include <cstddef>

#define N_NODES 50000
#define N_EDGES 800000
#define HID 128
#define KIN 288            // 2*HID + 32 edge features
#define TILE_E 128
#define TILE_N 128
#define SASTRIDE 300       // 300 % 32 = 12 -> conflict-free tf32 A-frag loads, 16B aligned rows
#define H1STRIDE 132       // 132 % 32 = 4  -> conflict-free A-frag loads
#define WSTRIDE  136       // 136 % 32 = 8  -> conflict-free B-frag loads
#define KSLAB 32
#define NTHREADS 256

// Scratch (static device allocations are allowed; cudaMalloc is not).
__device__ __align__(16) float g_node[(size_t)N_NODES * HID];
__device__ __align__(16) float g_cnt[N_NODES];

__device__ __forceinline__ float tf32r(float x) {
    unsigned u;
    asm("cvt.rna.tf32.f32 %0, %1;" : "=r"(u) : "f"(x));
    return __uint_as_float(u);
}

__device__ __forceinline__ float silu(float x) {
    return x * (1.0f / (1.0f + __expf(-x)));
}

__device__ __forceinline__ void mma8(float c[4],
                                     unsigned a0, unsigned a1, unsigned a2, unsigned a3,
                                     unsigned b0, unsigned b1) {
    asm volatile(
        "mma.sync.aligned.m16n8k8.row.col.f32.tf32.tf32.f32 "
        "{%0,%1,%2,%3}, {%4,%5,%6,%7}, {%8,%9}, {%0,%1,%2,%3};\n"
        : "+f"(c[0]), "+f"(c[1]), "+f"(c[2]), "+f"(c[3])
        : "r"(a0), "r"(a1), "r"(a2), "r"(a3), "r"(b0), "r"(b1));
}

// ---------------------------------------------------------------------------
// K1: zero accumulators
// ---------------------------------------------------------------------------
__global__ void zero_kernel() {
    int i = blockIdx.x * blockDim.x + threadIdx.x;
    int stride = gridDim.x * blockDim.x;
    float4 z = make_float4(0.f, 0.f, 0.f, 0.f);
    for (int v = i; v < (N_NODES * HID) / 4; v += stride)
        reinterpret_cast<float4*>(g_node)[v] = z;
    for (int v = i; v < N_NODES; v += stride)
        g_cnt[v] = 0.f;
}

// ---------------------------------------------------------------------------
// K2: fused edge MLP (288 -> 128 silu -> 128 silu) + scatter-add
// 128 edges per CTA, 8 warps, tf32 mma.sync.
// ---------------------------------------------------------------------------
__global__ void __launch_bounds__(NTHREADS, 1)
edge_kernel(const float* __restrict__ h, const int* __restrict__ eidx,
            const float* __restrict__ eattr,
            const float* __restrict__ w1, const float* __restrict__ b1,
            const float* __restrict__ w2, const float* __restrict__ b2) {
    extern __shared__ float smem[];
    float* sA  = smem;                        // [128][300] gathered features; reused as h1 [128][132]
    float* sW  = sA + TILE_E * SASTRIDE;      // [32][136] weight slab
    float* sB1 = sW + KSLAB * WSTRIDE;        // [128]
    float* sB2 = sB1 + HID;                   // [128]
    int*   srow = (int*)(sB2 + HID);          // [128]
    int*   scol = srow + TILE_E;              // [128]

    const int tid  = threadIdx.x;
    const int lane = tid & 31;
    const int wrp  = tid >> 5;
    const int t4   = lane & 3;
    const int g8   = lane >> 2;
    const int e0   = blockIdx.x * TILE_E;

    if (tid < TILE_E) {
        srow[tid] = eidx[e0 + tid];
        scol[tid] = eidx[N_EDGES + e0 + tid];
    }
    if (tid < HID) { sB1[tid] = b1[tid]; sB2[tid] = b2[tid]; }
    __syncthreads();

    // edge-count scatter
    if (tid < TILE_E) atomicAdd(&g_cnt[srow[tid]], 1.0f);

    // gather concat(h[row], h[col], edge_attr) -> sA, tf32-rounded
    for (int v = tid; v < TILE_E * 72; v += NTHREADS) {
        int el = v / 72;
        int k4 = (v - el * 72) * 4;
        const float* src;
        if (k4 < HID)          src = h + (size_t)srow[el] * HID + k4;
        else if (k4 < 2 * HID) src = h + (size_t)scol[el] * HID + (k4 - HID);
        else                   src = eattr + (size_t)(e0 + el) * 32 + (k4 - 2 * HID);
        float4 val = *reinterpret_cast<const float4*>(src);
        *reinterpret_cast<float4*>(sA + el * SASTRIDE + k4) =
            make_float4(tf32r(val.x), tf32r(val.y), tf32r(val.z), tf32r(val.w));
    }
    __syncthreads();

    float acc[16][4];
    const int arow = wrp * 16 + g8;

    // ----- layer 1: bias preload + GEMM K=288 -----
#pragma unroll
    for (int nt = 0; nt < 16; nt++) {
        float p = sB1[nt * 8 + 2 * t4], q = sB1[nt * 8 + 2 * t4 + 1];
        acc[nt][0] = p; acc[nt][1] = q; acc[nt][2] = p; acc[nt][3] = q;
    }

    for (int ks = 0; ks < KIN; ks += KSLAB) {
        for (int t = tid; t < KSLAB * 32; t += NTHREADS) {
            int r = t >> 5, c4 = (t & 31) << 2;
            float4 val = *reinterpret_cast<const float4*>(w1 + (size_t)(ks + r) * HID + c4);
            *reinterpret_cast<float4*>(sW + r * WSTRIDE + c4) =
                make_float4(tf32r(val.x), tf32r(val.y), tf32r(val.z), tf32r(val.w));
        }
        __syncthreads();
#pragma unroll
        for (int kk = 0; kk < KSLAB; kk += 8) {
            const float* ap = sA + arow * SASTRIDE + ks + kk + t4;
            unsigned a0 = __float_as_uint(ap[0]);
            unsigned a1 = __float_as_uint(ap[8 * SASTRIDE]);
            unsigned a2 = __float_as_uint(ap[4]);
            unsigned a3 = __float_as_uint(ap[8 * SASTRIDE + 4]);
            const float* bp = sW + (kk + t4) * WSTRIDE + g8;
#pragma unroll
            for (int nt = 0; nt < 16; nt++) {
                unsigned b0  = __float_as_uint(bp[nt * 8]);
                unsigned b1v = __float_as_uint(bp[4 * WSTRIDE + nt * 8]);
                mma8(acc[nt], a0, a1, a2, a3, b0, b1v);
            }
        }
        __syncthreads();
    }

    // silu -> h1 (reuse sA region with stride 132); each warp writes only its own 16 rows
#pragma unroll
    for (int nt = 0; nt < 16; nt++) {
        int c = nt * 8 + 2 * t4;
        sA[arow * H1STRIDE + c]           = tf32r(silu(acc[nt][0]));
        sA[arow * H1STRIDE + c + 1]       = tf32r(silu(acc[nt][1]));
        sA[(arow + 8) * H1STRIDE + c]     = tf32r(silu(acc[nt][2]));
        sA[(arow + 8) * H1STRIDE + c + 1] = tf32r(silu(acc[nt][3]));
    }

    // ----- layer 2: bias preload + GEMM K=128 -----
#pragma unroll
    for (int nt = 0; nt < 16; nt++) {
        float p = sB2[nt * 8 + 2 * t4], q = sB2[nt * 8 + 2 * t4 + 1];
        acc[nt][0] = p; acc[nt][1] = q; acc[nt][2] = p; acc[nt][3] = q;
    }

    for (int ks = 0; ks < HID; ks += KSLAB) {
        __syncthreads();   // prior slab consumed (1st iter: after GEMM1's final sync)
        for (int t = tid; t < KSLAB * 32; t += NTHREADS) {
            int r = t >> 5, c4 = (t & 31) << 2;
            float4 val = *reinterpret_cast<const float4*>(w2 + (size_t)(ks + r) * HID + c4);
            *reinterpret_cast<float4*>(sW + r * WSTRIDE + c4) =
                make_float4(tf32r(val.x), tf32r(val.y), tf32r(val.z), tf32r(val.w));
        }
        __syncthreads();
#pragma unroll
        for (int kk = 0; kk < KSLAB; kk += 8) {
            const float* ap = sA + arow * H1STRIDE + ks + kk + t4;   // h1 (own rows)
            unsigned a0 = __float_as_uint(ap[0]);
            unsigned a1 = __float_as_uint(ap[8 * H1STRIDE]);
            unsigned a2 = __float_as_uint(ap[4]);
            unsigned a3 = __float_as_uint(ap[8 * H1STRIDE + 4]);
            const float* bp = sW + (kk + t4) * WSTRIDE + g8;
#pragma unroll
            for (int nt = 0; nt < 16; nt++) {
                unsigned b0  = __float_as_uint(bp[nt * 8]);
                unsigned b1v = __float_as_uint(bp[4 * WSTRIDE + nt * 8]);
                mma8(acc[nt], a0, a1, a2, a3, b0, b1v);
            }
        }
    }

    // silu + vector-RED scatter to g_node
    const int row0 = srow[arow];
    const int row1 = srow[arow + 8];
#pragma unroll
    for (int nt = 0; nt < 16; nt++) {
        int c = nt * 8 + 2 * t4;
        float s0 = silu(acc[nt][0]), s1 = silu(acc[nt][1]);
        float s2 = silu(acc[nt][2]), s3 = silu(acc[nt][3]);
        float* p0 = g_node + (size_t)row0 * HID + c;
        float* p1 = g_node + (size_t)row1 * HID + c;
        asm volatile("red.global.add.v2.f32 [%0], {%1, %2};" :: "l"(p0), "f"(s0), "f"(s1) : "memory");
        asm volatile("red.global.add.v2.f32 [%0], {%1, %2};" :: "l"(p1), "f"(s2), "f"(s3) : "memory");
    }
}

// ---------------------------------------------------------------------------
// K3: node MLPs (mean -> silu(W1)+b1 -> W2+b2, two paths) + Gram-Schmidt + cross
// 128 nodes per CTA, tf32 mma for the 128x128 layer, fused 128->3 reduction.
// ---------------------------------------------------------------------------
__global__ void __launch_bounds__(NTHREADS, 2)
node_kernel(const float* __restrict__ w11, const float* __restrict__ b11,
            const float* __restrict__ w12, const float* __restrict__ b12,
            const float* __restrict__ w21, const float* __restrict__ b21,
            const float* __restrict__ w22, const float* __restrict__ b22,
            float* __restrict__ out) {
    extern __shared__ float smem[];
    float* sN   = smem;                        // [128][132] node means (tf32)
    float* sW   = sN + TILE_N * H1STRIDE;      // [32][136] weight slab
    float* sW2  = sW + KSLAB * WSTRIDE;        // [128*3] second-layer weights (+pad)
    float* sB1  = sW2 + 392;                   // [128]
    float* sVec = sB1 + HID;                   // [2][128][3]

    const int tid  = threadIdx.x;
    const int lane = tid & 31;
    const int wrp  = tid >> 5;
    const int t4   = lane & 3;
    const int g8   = lane >> 2;
    const int n0   = blockIdx.x * TILE_N;

    // stage node means (scatter-sum / max(cnt,1)), tf32-rounded
    for (int v = tid; v < TILE_N * 32; v += NTHREADS) {
        int nl = v >> 5, c4 = (v & 31) << 2;
        int ng = n0 + nl;
        float4 o = make_float4(0.f, 0.f, 0.f, 0.f);
        if (ng < N_NODES) {
            float sc = 1.0f / fmaxf(g_cnt[ng], 1.0f);
            float4 val = *reinterpret_cast<const float4*>(g_node + (size_t)ng * HID + c4);
            o = make_float4(tf32r(val.x * sc), tf32r(val.y * sc),
                            tf32r(val.z * sc), tf32r(val.w * sc));
        }
        *reinterpret_cast<float4*>(sN + nl * H1STRIDE + c4) = o;
    }

    const int arow = wrp * 16 + g8;

    for (int p = 0; p < 2; p++) {
        const float* W1 = p ? w21 : w11;
        const float* B1 = p ? b21 : b11;
        const float* W2 = p ? w22 : w12;
        const float* B2 = p ? b22 : b12;

        __syncthreads();    // prior path done with sB1/sW2/sW (and sN staged, 1st iter)
        if (tid < HID) sB1[tid] = B1[tid];
        for (int t = tid; t < HID * 3; t += NTHREADS) sW2[t] = W2[t];

        float acc[16][4];
#pragma unroll
        for (int nt = 0; nt < 16; nt++)
            acc[nt][0] = acc[nt][1] = acc[nt][2] = acc[nt][3] = 0.f;

        for (int ks = 0; ks < HID; ks += KSLAB) {
            __syncthreads();
            for (int t = tid; t < KSLAB * 32; t += NTHREADS) {
                int r = t >> 5, c4 = (t & 31) << 2;
                float4 val = *reinterpret_cast<const float4*>(W1 + (size_t)(ks + r) * HID + c4);
                *reinterpret_cast<float4*>(sW + r * WSTRIDE + c4) =
                    make_float4(tf32r(val.x), tf32r(val.y), tf32r(val.z), tf32r(val.w));
            }
            __syncthreads();
#pragma unroll
            for (int kk = 0; kk < KSLAB; kk += 8) {
                const float* ap = sN + arow * H1STRIDE + ks + kk + t4;
                unsigned a0 = __float_as_uint(ap[0]);
                unsigned a1 = __float_as_uint(ap[8 * H1STRIDE]);
                unsigned a2 = __float_as_uint(ap[4]);
                unsigned a3 = __float_as_uint(ap[8 * H1STRIDE + 4]);
                const float* bp = sW + (kk + t4) * WSTRIDE + g8;
#pragma unroll
                for (int nt = 0; nt < 16; nt++) {
                    unsigned b0  = __float_as_uint(bp[nt * 8]);
                    unsigned b1v = __float_as_uint(bp[4 * WSTRIDE + nt * 8]);
                    mma8(acc[nt], a0, a1, a2, a3, b0, b1v);
                }
            }
        }

        // layer 2 (128 -> 3): bias + silu on fragments, reduce over columns
        float p00 = 0.f, p01 = 0.f, p02 = 0.f;   // row arow
        float p10 = 0.f, p11 = 0.f, p12 = 0.f;   // row arow+8
#pragma unroll
        for (int nt = 0; nt < 16; nt++) {
            int c = nt * 8 + 2 * t4;
            float bb0 = sB1[c], bb1 = sB1[c + 1];
            float s0 = silu(acc[nt][0] + bb0), s1 = silu(acc[nt][1] + bb1);
            float s2 = silu(acc[nt][2] + bb0), s3 = silu(acc[nt][3] + bb1);
            float w0a = sW2[c * 3 + 0], w0b = sW2[c * 3 + 1], w0c = sW2[c * 3 + 2];
            float w1a = sW2[(c + 1) * 3 + 0], w1b = sW2[(c + 1) * 3 + 1], w1c = sW2[(c + 1) * 3 + 2];
            p00 += s0 * w0a + s1 * w1a;  p01 += s0 * w0b + s1 * w1b;  p02 += s0 * w0c + s1 * w1c;
            p10 += s2 * w0a + s3 * w1a;  p11 += s2 * w0b + s3 * w1b;  p12 += s2 * w0c + s3 * w1c;
        }
#pragma unroll
        for (int off = 1; off <= 2; off <<= 1) {
            p00 += __shfl_xor_sync(0xffffffffu, p00, off);
            p01 += __shfl_xor_sync(0xffffffffu, p01, off);
            p02 += __shfl_xor_sync(0xffffffffu, p02, off);
            p10 += __shfl_xor_sync(0xffffffffu, p10, off);
            p11 += __shfl_xor_sync(0xffffffffu, p11, off);
            p12 += __shfl_xor_sync(0xffffffffu, p12, off);
        }
        if (t4 == 0) {
            float c0 = __ldg(B2 + 0), c1 = __ldg(B2 + 1), c2 = __ldg(B2 + 2);
            float* d0 = sVec + ((size_t)p * TILE_N + arow) * 3;
            d0[0] = p00 + c0; d0[1] = p01 + c1; d0[2] = p02 + c2;
            float* d1 = sVec + ((size_t)p * TILE_N + arow + 8) * 3;
            d1[0] = p10 + c0; d1[1] = p11 + c1; d1[2] = p12 + c2;
        }
    }
    __syncthreads();

    // Gram-Schmidt + cross + output
    if (tid < TILE_N) {
        int ng = n0 + tid;
        if (ng < N_NODES) {
            float a0 = sVec[tid * 3], a1 = sVec[tid * 3 + 1], a2 = sVec[tid * 3 + 2];
            float b0 = sVec[(TILE_N + tid) * 3], b1 = sVec[(TILE_N + tid) * 3 + 1],
                  b2 = sVec[(TILE_N + tid) * 3 + 2];
            float n1 = fmaxf(sqrtf(a0 * a0 + a1 * a1 + a2 * a2), 1e-12f);
            float i1 = 1.0f / n1; a0 *= i1; a1 *= i1; a2 *= i1;
            float d = b0 * a0 + b1 * a1 + b2 * a2;
            b0 -= d * a0; b1 -= d * a1; b2 -= d * a2;
            float n2 = fmaxf(sqrtf(b0 * b0 + b1 * b1 + b2 * b2), 1e-12f);
            float i2 = 1.0f / n2; b0 *= i2; b1 *= i2; b2 *= i2;
            float c0 = a1 * b2 - a2 * b1;
            float c1 = a2 * b0 - a0 * b2;
            float c2 = a0 * b1 - a1 * b0;
            float* o = out + (size_t)ng * 9;
            o[0] = a0; o[1] = b0; o[2] = c0;
            o[3] = a1; o[4] = b1; o[5] = c1;
            o[6] = a2; o[7] = b2; o[8] = c2;
        }
    }
}

// ---------------------------------------------------------------------------
extern "C" void kernel_launch(void* const* d_in, const int* in_sizes, int n_in,
                              void* d_out, int out_size) {
    const float* h     = (const float*)d_in[0];
    // d_in[1] = x : unused by the reference computation
    const int*   eidx  = (const int*)d_in[2];
    const float* eattr = (const float*)d_in[3];
    const float* ew1   = (const float*)d_in[4];
    const float* eb1   = (const float*)d_in[5];
    const float* ew2   = (const float*)d_in[6];
    const float* eb2   = (const float*)d_in[7];
    const float* v1w1  = (const float*)d_in[8];
    const float* v1b1  = (const float*)d_in[9];
    const float* v1w2  = (const float*)d_in[10];
    const float* v1b2  = (const float*)d_in[11];
    const float* v2w1  = (const float*)d_in[12];
    const float* v2b1  = (const float*)d_in[13];
    const float* v2w2  = (const float*)d_in[14];
    const float* v2b2  = (const float*)d_in[15];
    float* out = (float*)d_out;

    const int smem_edge = (TILE_E * SASTRIDE + KSLAB * WSTRIDE + 2 * HID + 2 * TILE_E) * 4;
    const int smem_node = (TILE_N * H1STRIDE + KSLAB * WSTRIDE + 392 + HID + 2 * TILE_N * 3) * 4;

    cudaFuncSetAttribute(edge_kernel, cudaFuncAttributeMaxDynamicSharedMemorySize, smem_edge);
    cudaFuncSetAttribute(node_kernel, cudaFuncAttributeMaxDynamicSharedMemorySize, smem_node);

    zero_kernel<<<264, 256>>>();
    edge_kernel<<<N_EDGES / TILE_E, NTHREADS, smem_edge>>>(h, eidx, eattr, ew1, eb1, ew2, eb2);
    node_kernel<<<(N_NODES + TILE_N - 1) / TILE_N, NTHREADS, smem_node>>>(
        v1w1, v1b1, v1w2, v1b2, v2w1, v2b1, v2w2, v2b2, out);
}

// round 11
// speedup vs baseline: 4.3925x; 4.3925x over previous
#include <cuda_runtime.h>
#include <cuda_fp16.h>
#include <cstdint>
#include <cstddef>

#define N_NODES 50000
#define N_EDGES 800000
#define HID 128
#define EDGE_NF 32
#define TILE_E 128
#define TILE_N 128
#define NTHREADS 256

// ---- node kernel (tf32 mma.sync) strides ----
#define H1STRIDE 132
#define WSTRIDE  136
#define KSLAB 32

// ---- edge kernel geometry (fp16 m16n8k16) ----
#define ASTRIDE 296        // halves per A row; 148 words % 32 = 20 -> conflict-free
#define WSLAB_H 40         // halves per W^T row in a slab; 20 words % 32 = 20 -> conflict-free
#define SLAB_HALVES (128 * WSLAB_H)      // 5120 halves = 10240 B
#define SLAB_BYTES 10240
#define NS1 9              // K=288 -> 9 slabs of 32
#define NS2 4              // K=128 -> 4 slabs
#define NS_TOT 13
// smem byte offsets (edge kernel)
#define A_OFF    0                        // 128 rows x 592 B = 75776 B
#define W_OFF    75776                    // 3-slab ring = 30720 B
#define B1_OFF   106496                   // 512
#define B2_OFF   107008                   // 512
#define ROW_OFF  107520                   // 512
#define COL_OFF  108032                   // 512
#define SMEM_EDGE 108544

// device scratch (static allocation is allowed)
__device__ __align__(16) float g_node[(size_t)N_NODES * HID];
__device__ __align__(16) float g_cnt[N_NODES];
__device__ __align__(16) __half g_w1t[NS1 * SLAB_HALVES];   // W1^T fp16 slabs [j][n][kk(32)+pad8]
__device__ __align__(16) __half g_w2t[NS2 * SLAB_HALVES];
__device__ __align__(16) __half g_hh[(size_t)N_NODES * HID];        // h in fp16
__device__ __align__(16) __half g_eh[(size_t)N_EDGES * EDGE_NF];    // edge_attr in fp16

// ---------------- helpers ----------------
__device__ __forceinline__ float tf32r(float x) {
    unsigned u;
    asm("cvt.rna.tf32.f32 %0, %1;" : "=r"(u) : "f"(x));
    return __uint_as_float(u);
}
__device__ __forceinline__ float silu(float x) { return x * (1.0f / (1.0f + __expf(-x))); }

__device__ __forceinline__ uint32_t smem_to_u32(const void* p) {
    uint32_t a;
    asm("{ .reg .u64 t; cvta.to.shared.u64 t, %1; cvt.u32.u64 %0, t; }" : "=r"(a) : "l"(p));
    return a;
}
__device__ __forceinline__ void cpa16(uint32_t dst, const void* src) {
    asm volatile("cp.async.cg.shared.global [%0], [%1], 16;" :: "r"(dst), "l"(src));
}
__device__ __forceinline__ void cpa_commit() { asm volatile("cp.async.commit_group;"); }
template <int N>
__device__ __forceinline__ void cpa_wait() { asm volatile("cp.async.wait_group %0;" :: "n"(N)); }

// fp16 m16n8k16 mma with f32 accumulation
__device__ __forceinline__ void mma16(float c[4],
                                      uint32_t a0, uint32_t a1, uint32_t a2, uint32_t a3,
                                      uint32_t b0, uint32_t b1) {
    asm volatile(
        "mma.sync.aligned.m16n8k16.row.col.f32.f16.f16.f32 "
        "{%0,%1,%2,%3}, {%4,%5,%6,%7}, {%8,%9}, {%0,%1,%2,%3};\n"
        : "+f"(c[0]), "+f"(c[1]), "+f"(c[2]), "+f"(c[3])
        : "r"(a0), "r"(a1), "r"(a2), "r"(a3), "r"(b0), "r"(b1));
}
// tf32 m16n8k8 (node kernel)
__device__ __forceinline__ void mma8(float c[4],
                                     unsigned a0, unsigned a1, unsigned a2, unsigned a3,
                                     unsigned b0, unsigned b1) {
    asm volatile(
        "mma.sync.aligned.m16n8k8.row.col.f32.tf32.tf32.f32 "
        "{%0,%1,%2,%3}, {%4,%5,%6,%7}, {%8,%9}, {%0,%1,%2,%3};\n"
        : "+f"(c[0]), "+f"(c[1]), "+f"(c[2]), "+f"(c[3])
        : "r"(a0), "r"(a1), "r"(a2), "r"(a3), "r"(b0), "r"(b1));
}

// ---------------------------------------------------------------------------
// K1a: zero accumulators + convert h / edge_attr to fp16
// ---------------------------------------------------------------------------
__global__ void prep_kernel(const float* __restrict__ h, const float* __restrict__ eattr) {
    int i = blockIdx.x * blockDim.x + threadIdx.x;
    int stride = gridDim.x * blockDim.x;
    float4 z = make_float4(0.f, 0.f, 0.f, 0.f);
    for (int v = i; v < (N_NODES * HID) / 4; v += stride)
        reinterpret_cast<float4*>(g_node)[v] = z;
    for (int v = i; v < N_NODES; v += stride) g_cnt[v] = 0.f;
    // h -> fp16
    for (int v = i; v < (N_NODES * HID) / 4; v += stride) {
        float4 val = reinterpret_cast<const float4*>(h)[v];
        __half2 p0 = __floats2half2_rn(val.x, val.y);
        __half2 p1 = __floats2half2_rn(val.z, val.w);
        reinterpret_cast<uint2*>(g_hh)[v] = make_uint2(*(uint32_t*)&p0, *(uint32_t*)&p1);
    }
    // edge_attr -> fp16
    for (long v = i; v < ((long)N_EDGES * EDGE_NF) / 4; v += stride) {
        float4 val = reinterpret_cast<const float4*>(eattr)[v];
        __half2 p0 = __floats2half2_rn(val.x, val.y);
        __half2 p1 = __floats2half2_rn(val.z, val.w);
        reinterpret_cast<uint2*>(g_eh)[v] = make_uint2(*(uint32_t*)&p0, *(uint32_t*)&p1);
    }
}
// K1b: zero weight slabs (pads deterministic), then fill transposed fp16 weights
__global__ void prep_w_kernel(const float* __restrict__ w1, const float* __restrict__ w2) {
    int i = blockIdx.x * blockDim.x + threadIdx.x;
    int stride = gridDim.x * blockDim.x;
    for (int v = i; v < NS1 * SLAB_HALVES; v += stride) g_w1t[v] = __half(0.f);
    for (int v = i; v < NS2 * SLAB_HALVES; v += stride) g_w2t[v] = __half(0.f);
}
__global__ void prep_w2_kernel(const float* __restrict__ w1, const float* __restrict__ w2) {
    int i = blockIdx.x * blockDim.x + threadIdx.x;
    int stride = gridDim.x * blockDim.x;
    // w1 [288,128] row-major -> slab j: [n][kk] = w1[32j+kk][n]
    for (int v = i; v < 288 * 128; v += stride) {
        int k = v >> 7, n = v & 127;
        int j = k >> 5, kk = k & 31;
        g_w1t[j * SLAB_HALVES + n * WSLAB_H + kk] = __float2half(w1[v]);
    }
    for (int v = i; v < 128 * 128; v += stride) {
        int k = v >> 7, n = v & 127;
        int j = k >> 5, kk = k & 31;
        g_w2t[j * SLAB_HALVES + n * WSLAB_H + kk] = __float2half(w2[v]);
    }
}

// ---------------------------------------------------------------------------
// compute one K=32 slab (two k16 steps) for the edge kernel
// ---------------------------------------------------------------------------
__device__ __forceinline__ void compute_slab(float acc[16][4],
                                             const __half* sAh, const __half* sWb,
                                             int acol0, int row0, int row1,
                                             int t4, int g8) {
#pragma unroll
    for (int ki = 0; ki < 2; ki++) {
        const int kb = acol0 + ki * 16;
        const int ksub = ki * 16;
        const uint32_t* ap0 = (const uint32_t*)(sAh + row0 * ASTRIDE + kb + 2 * t4);
        const uint32_t* ap1 = (const uint32_t*)(sAh + row1 * ASTRIDE + kb + 2 * t4);
        uint32_t a0 = ap0[0], a2 = ap0[4];   // +8 halves = +4 words
        uint32_t a1 = ap1[0], a3 = ap1[4];
#pragma unroll
        for (int nt = 0; nt < 16; nt++) {
            const uint32_t* bp = (const uint32_t*)(sWb + (nt * 8 + g8) * WSLAB_H + ksub + 2 * t4);
            mma16(acc[nt], a0, a1, a2, a3, bp[0], bp[4]);
        }
    }
}

// ---------------------------------------------------------------------------
// K2: fused edge MLP (fp16 m16n8k16) + scatter
// ---------------------------------------------------------------------------
__global__ void __launch_bounds__(NTHREADS, 2)
edge_kernel(const int* __restrict__ eidx,
            const float* __restrict__ b1, const float* __restrict__ b2) {
    extern __shared__ __align__(16) char smem_raw[];
    const uint32_t su = smem_to_u32(smem_raw);
    __half* sAh = (__half*)(smem_raw + A_OFF);
    __half* sWh = (__half*)(smem_raw + W_OFF);
    float* sB1 = (float*)(smem_raw + B1_OFF);
    float* sB2 = (float*)(smem_raw + B2_OFF);
    int* srow = (int*)(smem_raw + ROW_OFF);
    int* scol = (int*)(smem_raw + COL_OFF);

    const int tid = threadIdx.x;
    const int lane = tid & 31;
    const int wid = tid >> 5;
    const int t4 = lane & 3;
    const int g8 = lane >> 2;
    const int e0 = blockIdx.x * TILE_E;

    if (tid < TILE_E) {
        srow[tid] = eidx[e0 + tid];
        scol[tid] = eidx[N_EDGES + e0 + tid];
    }
    if (tid < HID) { sB1[tid] = b1[tid]; sB2[tid] = b2[tid]; }
    __syncthreads();     // srow/scol visible for gather

    if (tid < TILE_E) atomicAdd(&g_cnt[srow[tid]], 1.0f);

    // gather concat(h16[row], h16[col], ea16) -> A tile via cp.async (group G, committed FIRST)
    // per edge: 16 + 16 + 4 = 36 chunks of 16B
    for (int v = tid; v < TILE_E * 36; v += NTHREADS) {
        int el = v / 36;
        int c = v - el * 36;
        const char* src;
        if (c < 16)      src = (const char*)(g_hh + (size_t)srow[el] * HID) + c * 16;
        else if (c < 32) src = (const char*)(g_hh + (size_t)scol[el] * HID) + (c - 16) * 16;
        else             src = (const char*)(g_eh + (size_t)(e0 + el) * EDGE_NF) + (c - 32) * 16;
        cpa16(su + A_OFF + el * (ASTRIDE * 2) + c * 16, src);
    }
    cpa_commit();

    // prologue: W slabs 0 and 1 via cp.async (each its own group)
    {
        const char* src = (const char*)g_w1t;
        for (int t = tid; t < SLAB_BYTES / 16; t += NTHREADS)
            cpa16(su + W_OFF + t * 16, src + t * 16);
        cpa_commit();
        src = (const char*)(g_w1t + SLAB_HALVES);
        for (int t = tid; t < SLAB_BYTES / 16; t += NTHREADS)
            cpa16(su + W_OFF + SLAB_BYTES + t * 16, src + t * 16);
        cpa_commit();
    }

    const int arow = wid * 16;
    const int row0 = arow + g8;
    const int row1 = row0 + 8;

    float acc[16][4];

    for (int s = 0; s < NS_TOT; s++) {
        if (s < NS_TOT - 1) cpa_wait<1>(); else cpa_wait<0>();
        __syncthreads();
        // prefetch slab s+2 into ring buffer (s+2)%3 (its previous user, slab s-1, is done)
        if (s + 2 < NS_TOT) {
            int j = s + 2;
            const char* src = (j < NS1) ? (const char*)(g_w1t + j * SLAB_HALVES)
                                        : (const char*)(g_w2t + (j - NS1) * SLAB_HALVES);
            uint32_t dst = su + W_OFF + (j % 3) * SLAB_BYTES;
            for (int t = tid; t < SLAB_BYTES / 16; t += NTHREADS)
                cpa16(dst + t * 16, src + t * 16);
            cpa_commit();
        }

        if (s == 0) {
            // bias preload for layer 1
#pragma unroll
            for (int nt = 0; nt < 16; nt++) {
                float p = sB1[nt * 8 + 2 * t4], q = sB1[nt * 8 + 2 * t4 + 1];
                acc[nt][0] = p; acc[nt][1] = q; acc[nt][2] = p; acc[nt][3] = q;
            }
        }
        if (s == NS1) {
            // epilogue 1: silu(acc) -> h1 (fp16) into A cols 0..127 (own rows only)
#pragma unroll
            for (int nt = 0; nt < 16; nt++) {
                int c = nt * 8 + 2 * t4;
                __half2 v0 = __floats2half2_rn(silu(acc[nt][0]), silu(acc[nt][1]));
                __half2 v1 = __floats2half2_rn(silu(acc[nt][2]), silu(acc[nt][3]));
                *(uint32_t*)(sAh + row0 * ASTRIDE + c) = *(uint32_t*)&v0;
                *(uint32_t*)(sAh + row1 * ASTRIDE + c) = *(uint32_t*)&v1;
            }
            // bias preload for layer 2
#pragma unroll
            for (int nt = 0; nt < 16; nt++) {
                float p = sB2[nt * 8 + 2 * t4], q = sB2[nt * 8 + 2 * t4 + 1];
                acc[nt][0] = p; acc[nt][1] = q; acc[nt][2] = p; acc[nt][3] = q;
            }
        }

        int acol0 = (s < NS1) ? s * 32 : (s - NS1) * 32;
        compute_slab(acc, sAh, sWh + (s % 3) * SLAB_HALVES, acol0, row0, row1, t4, g8);
    }

    // epilogue 2: silu + v2 RED scatter
    const int n0 = srow[row0];
    const int n1 = srow[row1];
#pragma unroll
    for (int nt = 0; nt < 16; nt++) {
        int c = nt * 8 + 2 * t4;
        float s0 = silu(acc[nt][0]), s1 = silu(acc[nt][1]);
        float s2 = silu(acc[nt][2]), s3 = silu(acc[nt][3]);
        float* p0 = g_node + (size_t)n0 * HID + c;
        float* p1 = g_node + (size_t)n1 * HID + c;
        asm volatile("red.global.add.v2.f32 [%0], {%1, %2};" :: "l"(p0), "f"(s0), "f"(s1) : "memory");
        asm volatile("red.global.add.v2.f32 [%0], {%1, %2};" :: "l"(p1), "f"(s2), "f"(s3) : "memory");
    }
}

// ---------------------------------------------------------------------------
// K3: node MLPs + Gram-Schmidt + cross (tf32 mma.sync)
// ---------------------------------------------------------------------------
__global__ void __launch_bounds__(NTHREADS, 2)
node_kernel(const float* __restrict__ w11, const float* __restrict__ b11,
            const float* __restrict__ w12, const float* __restrict__ b12,
            const float* __restrict__ w21, const float* __restrict__ b21,
            const float* __restrict__ w22, const float* __restrict__ b22,
            float* __restrict__ out) {
    extern __shared__ float smemn[];
    float* sN   = smemn;
    float* sW   = sN + TILE_N * H1STRIDE;
    float* sW2  = sW + KSLAB * WSTRIDE;
    float* sB1  = sW2 + 392;
    float* sVec = sB1 + HID;

    const int tid  = threadIdx.x;
    const int lane = tid & 31;
    const int wrp  = tid >> 5;
    const int t4   = lane & 3;
    const int g8   = lane >> 2;
    const int n0   = blockIdx.x * TILE_N;

    for (int v = tid; v < TILE_N * 32; v += NTHREADS) {
        int nl = v >> 5, c4 = (v & 31) << 2;
        int ng = n0 + nl;
        float4 o = make_float4(0.f, 0.f, 0.f, 0.f);
        if (ng < N_NODES) {
            float sc = 1.0f / fmaxf(g_cnt[ng], 1.0f);
            float4 val = *reinterpret_cast<const float4*>(g_node + (size_t)ng * HID + c4);
            o = make_float4(tf32r(val.x * sc), tf32r(val.y * sc),
                            tf32r(val.z * sc), tf32r(val.w * sc));
        }
        *reinterpret_cast<float4*>(sN + nl * H1STRIDE + c4) = o;
    }

    const int arow = wrp * 16 + g8;

    for (int p = 0; p < 2; p++) {
        const float* W1 = p ? w21 : w11;
        const float* B1 = p ? b21 : b11;
        const float* W2 = p ? w22 : w12;
        const float* B2 = p ? b22 : b12;

        __syncthreads();
        if (tid < HID) sB1[tid] = B1[tid];
        for (int t = tid; t < HID * 3; t += NTHREADS) sW2[t] = W2[t];

        float acc[16][4];
#pragma unroll
        for (int nt = 0; nt < 16; nt++)
            acc[nt][0] = acc[nt][1] = acc[nt][2] = acc[nt][3] = 0.f;

        for (int ks = 0; ks < HID; ks += KSLAB) {
            __syncthreads();
            for (int t = tid; t < KSLAB * 32; t += NTHREADS) {
                int r = t >> 5, c4 = (t & 31) << 2;
                float4 val = *reinterpret_cast<const float4*>(W1 + (size_t)(ks + r) * HID + c4);
                *reinterpret_cast<float4*>(sW + r * WSTRIDE + c4) =
                    make_float4(tf32r(val.x), tf32r(val.y), tf32r(val.z), tf32r(val.w));
            }
            __syncthreads();
#pragma unroll
            for (int kk = 0; kk < KSLAB; kk += 8) {
                const float* ap = sN + arow * H1STRIDE + ks + kk + t4;
                unsigned a0 = __float_as_uint(ap[0]);
                unsigned a1 = __float_as_uint(ap[8 * H1STRIDE]);
                unsigned a2 = __float_as_uint(ap[4]);
                unsigned a3 = __float_as_uint(ap[8 * H1STRIDE + 4]);
                const float* bp = sW + (kk + t4) * WSTRIDE + g8;
#pragma unroll
                for (int nt = 0; nt < 16; nt++) {
                    unsigned b0  = __float_as_uint(bp[nt * 8]);
                    unsigned b1v = __float_as_uint(bp[4 * WSTRIDE + nt * 8]);
                    mma8(acc[nt], a0, a1, a2, a3, b0, b1v);
                }
            }
        }

        float p00 = 0.f, p01 = 0.f, p02 = 0.f;
        float p10 = 0.f, p11 = 0.f, p12 = 0.f;
#pragma unroll
        for (int nt = 0; nt < 16; nt++) {
            int c = nt * 8 + 2 * t4;
            float bb0 = sB1[c], bb1 = sB1[c + 1];
            float s0 = silu(acc[nt][0] + bb0), s1 = silu(acc[nt][1] + bb1);
            float s2 = silu(acc[nt][2] + bb0), s3 = silu(acc[nt][3] + bb1);
            float w0a = sW2[c * 3 + 0], w0b = sW2[c * 3 + 1], w0c = sW2[c * 3 + 2];
            float w1a = sW2[(c + 1) * 3 + 0], w1b = sW2[(c + 1) * 3 + 1], w1c = sW2[(c + 1) * 3 + 2];
            p00 += s0 * w0a + s1 * w1a;  p01 += s0 * w0b + s1 * w1b;  p02 += s0 * w0c + s1 * w1c;
            p10 += s2 * w0a + s3 * w1a;  p11 += s2 * w0b + s3 * w1b;  p12 += s2 * w0c + s3 * w1c;
        }
#pragma unroll
        for (int off = 1; off <= 2; off <<= 1) {
            p00 += __shfl_xor_sync(0xffffffffu, p00, off);
            p01 += __shfl_xor_sync(0xffffffffu, p01, off);
            p02 += __shfl_xor_sync(0xffffffffu, p02, off);
            p10 += __shfl_xor_sync(0xffffffffu, p10, off);
            p11 += __shfl_xor_sync(0xffffffffu, p11, off);
            p12 += __shfl_xor_sync(0xffffffffu, p12, off);
        }
        if (t4 == 0) {
            float c0 = __ldg(B2 + 0), c1 = __ldg(B2 + 1), c2 = __ldg(B2 + 2);
            float* d0 = sVec + ((size_t)p * TILE_N + arow) * 3;
            d0[0] = p00 + c0; d0[1] = p01 + c1; d0[2] = p02 + c2;
            float* d1 = sVec + ((size_t)p * TILE_N + arow + 8) * 3;
            d1[0] = p10 + c0; d1[1] = p11 + c1; d1[2] = p12 + c2;
        }
    }
    __syncthreads();

    if (tid < TILE_N) {
        int ng = n0 + tid;
        if (ng < N_NODES) {
            float a0 = sVec[tid * 3], a1 = sVec[tid * 3 + 1], a2 = sVec[tid * 3 + 2];
            float b0 = sVec[(TILE_N + tid) * 3], b1 = sVec[(TILE_N + tid) * 3 + 1],
                  b2 = sVec[(TILE_N + tid) * 3 + 2];
            float n1 = fmaxf(sqrtf(a0 * a0 + a1 * a1 + a2 * a2), 1e-12f);
            float i1 = 1.0f / n1; a0 *= i1; a1 *= i1; a2 *= i1;
            float d = b0 * a0 + b1 * a1 + b2 * a2;
            b0 -= d * a0; b1 -= d * a1; b2 -= d * a2;
            float n2 = fmaxf(sqrtf(b0 * b0 + b1 * b1 + b2 * b2), 1e-12f);
            float i2 = 1.0f / n2; b0 *= i2; b1 *= i2; b2 *= i2;
            float c0 = a1 * b2 - a2 * b1;
            float c1 = a2 * b0 - a0 * b2;
            float c2 = a0 * b1 - a1 * b0;
            float* o = out + (size_t)ng * 9;
            o[0] = a0; o[1] = b0; o[2] = c0;
            o[3] = a1; o[4] = b1; o[5] = c1;
            o[6] = a2; o[7] = b2; o[8] = c2;
        }
    }
}

// ---------------------------------------------------------------------------
extern "C" void kernel_launch(void* const* d_in, const int* in_sizes, int n_in,
                              void* d_out, int out_size) {
    const float* h     = (const float*)d_in[0];
    const int*   eidx  = (const int*)d_in[2];
    const float* eattr = (const float*)d_in[3];
    const float* ew1   = (const float*)d_in[4];
    const float* eb1   = (const float*)d_in[5];
    const float* ew2   = (const float*)d_in[6];
    const float* eb2   = (const float*)d_in[7];
    const float* v1w1  = (const float*)d_in[8];
    const float* v1b1  = (const float*)d_in[9];
    const float* v1w2  = (const float*)d_in[10];
    const float* v1b2  = (const float*)d_in[11];
    const float* v2w1  = (const float*)d_in[12];
    const float* v2b1  = (const float*)d_in[13];
    const float* v2w2  = (const float*)d_in[14];
    const float* v2b2  = (const float*)d_in[15];
    float* out = (float*)d_out;

    const int smem_node = (TILE_N * H1STRIDE + KSLAB * WSTRIDE + 392 + HID + 2 * TILE_N * 3) * 4;

    cudaFuncSetAttribute(edge_kernel, cudaFuncAttributeMaxDynamicSharedMemorySize, SMEM_EDGE);
    cudaFuncSetAttribute(node_kernel, cudaFuncAttributeMaxDynamicSharedMemorySize, smem_node);

    prep_kernel<<<296, 256>>>(h, eattr);
    prep_w_kernel<<<64, 256>>>(ew1, ew2);
    prep_w2_kernel<<<64, 256>>>(ew1, ew2);
    edge_kernel<<<N_EDGES / TILE_E, NTHREADS, SMEM_EDGE>>>(eidx, eb1, eb2);
    node_kernel<<<(N_NODES + TILE_N - 1) / TILE_N, NTHREADS, smem_node>>>(
        v1w1, v1b1, v1w2, v1b2, v2w1, v2b1, v2w2, v2b2, out);
}